// round 14
// baseline (speedup 1.0000x reference)
#include <cuda_runtime.h>
#include <cuda_bf16.h>
#include <cstdint>

#define N_NODES 50000
#define N_EDGES 800000
#define HD_SCALE 0.17677669529663687f   // 1/sqrt(32)
#define SCAN_T 1024
#define KP 136                           // padded bf16 row stride (272B)

// ---------------- scratch (device globals: no allocation allowed) ----------
__device__ __align__(256) float g_Q[N_NODES * 128];
__device__ __align__(256) float g_K[N_NODES * 128];
__device__ __align__(256) float g_V[N_NODES * 128];
__device__ __align__(256) float g_biasS[N_EDGES * 4];
__device__ __align__(256) float g_agg[N_NODES * 128];
__device__ __align__(256) float g_Wf[128 * 128];
__device__ __align__(256) float g_bf[128];
__device__ __align__(256) int   g_cnt[N_NODES];
__device__ __align__(256) int   g_off[N_NODES + 1];
__device__ __align__(256) int   g_pos[N_NODES];
__device__ __align__(256) int   g_src[N_EDGES];

// ---------------- mma.sync helpers (arch-neutral PTX, sm_80+) ---------------
__device__ __forceinline__ uint32_t smem_u32(const void* p) {
    uint32_t a;
    asm("{ .reg .u64 t; cvta.to.shared.u64 t, %1; cvt.u32.u64 %0, t; }"
        : "=r"(a) : "l"(p));
    return a;
}
#define LDM_X4(r, addr)                                                        \
    asm volatile("ldmatrix.sync.aligned.m8n8.x4.shared.b16 {%0,%1,%2,%3}, [%4];" \
                 : "=r"((r)[0]), "=r"((r)[1]), "=r"((r)[2]), "=r"((r)[3])      \
                 : "r"(addr))
#define MMA_B16(c, a, b0, b1)                                                  \
    asm volatile("mma.sync.aligned.m16n8k16.row.col.f32.bf16.bf16.f32 "        \
                 "{%0,%1,%2,%3}, {%4,%5,%6,%7}, {%8,%9}, {%0,%1,%2,%3};"       \
                 : "+f"((c)[0]), "+f"((c)[1]), "+f"((c)[2]), "+f"((c)[3])      \
                 : "r"((a)[0]), "r"((a)[1]), "r"((a)[2]), "r"((a)[3]),         \
                   "r"(b0), "r"(b1))

// smem layout: A tiles 64 x KP bf16, B tiles 128 x KP bf16. 104448 B total
// -> 2 blocks/SM (fills of one block overlap sweeps of the other).
#define A_BYTES (64 * KP * 2)           // 17408
#define B_BYTES (128 * KP * 2)          // 34816
#define SM_AH 0
#define SM_AL (SM_AH + A_BYTES)
#define SM_BH (SM_AL + A_BYTES)
#define SM_BL (SM_BH + B_BYTES)
#define SM_MMA_TOT (SM_BL + B_BYTES)    // 104448

__device__ __forceinline__ uint32_t pack_bf2(float a, float b) {
    __nv_bfloat162 h = __floats2bfloat162_rn(a, b);
    return *(uint32_t*)&h;
}

__device__ __forceinline__ void split_store(char* hb, char* lb, int row, int col,
                                            float v) {
    __nv_bfloat16 hi = __float2bfloat16(v);
    __nv_bfloat16 lo = __float2bfloat16(v - __bfloat162float(hi));
    int off = (row * KP + col) * 2;
    *(__nv_bfloat16*)(hb + off) = hi;
    *(__nv_bfloat16*)(lb + off) = lo;
}

// A tile: 64 rows of src starting at r0 (row-clamped), packed 4B stores.
__device__ __forceinline__ void load_A64(char* sm, const float* __restrict__ src,
                                         int r0, int tid) {
    for (int i = tid; i < 64 * 32; i += 256) {
        int r = i >> 5, c = (i & 31) * 4;
        int gr = r0 + r; if (gr >= N_NODES) gr = N_NODES - 1;
        float4 v = *(const float4*)(src + (size_t)gr * 128 + c);
        float h0 = __bfloat162float(__float2bfloat16(v.x));
        float h1 = __bfloat162float(__float2bfloat16(v.y));
        float h2 = __bfloat162float(__float2bfloat16(v.z));
        float h3 = __bfloat162float(__float2bfloat16(v.w));
        int off = (r * KP + c) * 2;
        *(uint32_t*)(sm + SM_AH + off)     = pack_bf2(v.x, v.y);
        *(uint32_t*)(sm + SM_AH + off + 4) = pack_bf2(v.z, v.w);
        *(uint32_t*)(sm + SM_AL + off)     = pack_bf2(v.x - h0, v.y - h1);
        *(uint32_t*)(sm + SM_AL + off + 4) = pack_bf2(v.z - h2, v.w - h3);
    }
}
// B tile as n-major (row n holds 128 k-values): W is k x n row-major.
__device__ __forceinline__ void load_B(char* sm, const float* __restrict__ W,
                                       int tid) {
    for (int i = tid; i < 128 * 32; i += 256) {
        int k = i >> 5, n0 = (i & 31) * 4;
        float4 v = *(const float4*)(W + k * 128 + n0);
        split_store(sm + SM_BH, sm + SM_BL, n0 + 0, k, v.x);
        split_store(sm + SM_BH, sm + SM_BL, n0 + 1, k, v.y);
        split_store(sm + SM_BH, sm + SM_BL, n0 + 2, k, v.z);
        split_store(sm + SM_BH, sm + SM_BL, n0 + 3, k, v.w);
    }
}

// K=128 sweep; warp owns a 16x64 tile (mB in {0,16,32,48}, nB in {0,64}).
__device__ __forceinline__ void mma_sweep64(uint32_t smb, int lane, int mB, int nB,
                                            float acc[8][4]) {
    int aRow = lane & 15;
    int aKH  = (lane >> 4) * 8;
    int bRow = (lane & 7) + ((lane >> 4) << 3);
    int bKH  = ((lane >> 3) & 1) * 8;
    #pragma unroll
    for (int ks = 0; ks < 8; ks++) {
        int k0 = ks * 16;
        uint32_t ah[4], al[4], bh[4][4], bl[4][4];
        {
            uint32_t off = (uint32_t)((mB + aRow) * KP + k0 + aKH) * 2;
            LDM_X4(ah, smb + SM_AH + off);
            LDM_X4(al, smb + SM_AL + off);
        }
        #pragma unroll
        for (int p = 0; p < 4; p++) {
            uint32_t off = (uint32_t)((nB + p * 16 + bRow) * KP + k0 + bKH) * 2;
            LDM_X4(bh[p], smb + SM_BH + off);
            LDM_X4(bl[p], smb + SM_BL + off);
        }
        #pragma unroll
        for (int nt = 0; nt < 8; nt++) {
            int p = nt >> 1, q = (nt & 1) * 2;
            MMA_B16(acc[nt], ah, bh[p][q], bh[p][q + 1]);
            MMA_B16(acc[nt], ah, bl[p][q], bl[p][q + 1]);
            MMA_B16(acc[nt], al, bh[p][q], bh[p][q + 1]);
        }
    }
}

// ---------------- fused QKV GEMM: A(x) staged once, loop over 3 W -----------
__global__ __launch_bounds__(256) void k_qkv_mma(const float* __restrict__ x,
                                                 const float* __restrict__ Wq,
                                                 const float* __restrict__ Wk,
                                                 const float* __restrict__ Wv) {
    extern __shared__ char sm[];
    int tid = threadIdx.x, lane = tid & 31, w = tid >> 5;
    int mB = (w >> 1) * 16, nB = (w & 1) * 64;
    int r0 = blockIdx.x * 64;
    uint32_t smb = smem_u32(sm);

    load_A64(sm, x, r0, tid);

    int gq = lane >> 2, tq = lane & 3;
    #pragma unroll
    for (int m = 0; m < 3; m++) {
        const float* W = (m == 0) ? Wq : (m == 1) ? Wk : Wv;
        float* out = (m == 0) ? g_Q : (m == 1) ? g_K : g_V;
        __syncthreads();
        load_B(sm, W, tid);
        __syncthreads();

        float acc[8][4];
        #pragma unroll
        for (int nt = 0; nt < 8; nt++)
            #pragma unroll
            for (int i = 0; i < 4; i++) acc[nt][i] = 0.f;

        mma_sweep64(smb, lane, mB, nB, acc);

        #pragma unroll
        for (int nt = 0; nt < 8; nt++) {
            int col = nB + nt * 8 + tq * 2;
            int row0 = r0 + mB + gq;
            if (row0 < N_NODES)
                *(float2*)(out + (size_t)row0 * 128 + col) =
                    make_float2(acc[nt][0], acc[nt][1]);
            int row1 = row0 + 8;
            if (row1 < N_NODES)
                *(float2*)(out + (size_t)row1 * 128 + col) =
                    make_float2(acc[nt][2], acc[nt][3]);
        }
    }
}

// ---------------- output GEMM: relu(x@Wm_top + agg@Wf + bf), 2 passes --------
__global__ __launch_bounds__(256) void k_out_mma(const float* __restrict__ x,
                                                 const float* __restrict__ Wm,
                                                 float* __restrict__ out) {
    extern __shared__ char sm[];
    int tid = threadIdx.x, lane = tid & 31, w = tid >> 5;
    int mB = (w >> 1) * 16, nB = (w & 1) * 64;
    int r0 = blockIdx.x * 64;
    uint32_t smb = smem_u32(sm);

    float acc[8][4];
    #pragma unroll
    for (int nt = 0; nt < 8; nt++)
        #pragma unroll
        for (int i = 0; i < 4; i++) acc[nt][i] = 0.f;

    #pragma unroll
    for (int pass = 0; pass < 2; pass++) {
        const float* A = pass ? (const float*)g_agg : x;
        const float* B = pass ? (const float*)g_Wf : Wm;   // Wm rows 0-127 = x part
        __syncthreads();
        load_A64(sm, A, r0, tid);
        load_B(sm, B, tid);
        __syncthreads();
        mma_sweep64(smb, lane, mB, nB, acc);
    }

    int gq = lane >> 2, tq = lane & 3;
    #pragma unroll
    for (int nt = 0; nt < 8; nt++) {
        int col = nB + nt * 8 + tq * 2;
        float b0 = g_bf[col], b1 = g_bf[col + 1];
        int row0 = r0 + mB + gq;
        if (row0 < N_NODES)
            *(float2*)(out + (size_t)row0 * 128 + col) =
                make_float2(fmaxf(acc[nt][0] + b0, 0.f),
                            fmaxf(acc[nt][1] + b1, 0.f));
        int row1 = row0 + 8;
        if (row1 < N_NODES)
            *(float2*)(out + (size_t)row1 * 128 + col) =
                make_float2(fmaxf(acc[nt][2] + b0, 0.f),
                            fmaxf(acc[nt][3] + b1, 0.f));
    }
}

// ---------------- init / hist / scan / bucket / fusew ------------------------
__global__ void k_init() {
    int i = blockIdx.x * 256 + threadIdx.x;
    if (i < N_NODES) g_cnt[i] = 0;
}

__global__ __launch_bounds__(256) void k_hist(const int* __restrict__ ei) {
    int e = blockIdx.x * 256 + threadIdx.x;
    if (e >= N_EDGES) return;
    atomicAdd(&g_cnt[ei[N_EDGES + e]], 1);
}

__global__ void k_fusew(const float* __restrict__ Wo, const float* __restrict__ Wm,
                        const float* __restrict__ bo, const float* __restrict__ bm) {
    int r = blockIdx.x, j = threadIdx.x;
    float acc = 0.f;
    #pragma unroll 8
    for (int k = 0; k < 128; k++)
        acc += Wo[r * 128 + k] * Wm[(128 + k) * 128 + j];
    g_Wf[r * 128 + j] = acc;
    if (r == 0) {
        float b = bm[j];
        #pragma unroll 8
        for (int k = 0; k < 128; k++)
            b += bo[k] * Wm[(128 + k) * 128 + j];
        g_bf[j] = b;
    }
}

__global__ __launch_bounds__(SCAN_T) void k_scan() {
    __shared__ int sh[SCAN_T];
    int t = threadIdx.x;
    const int CHUNK = (N_NODES + SCAN_T - 1) / SCAN_T;
    int beg = t * CHUNK;
    int end = beg + CHUNK < N_NODES ? beg + CHUNK : N_NODES;
    int s = 0;
    for (int i = beg; i < end; i++) s += g_cnt[i];
    sh[t] = s;
    __syncthreads();
    for (int o = 1; o < SCAN_T; o <<= 1) {
        int v = (t >= o) ? sh[t - o] : 0;
        __syncthreads();
        sh[t] += v;
        __syncthreads();
    }
    int run = (t > 0) ? sh[t - 1] : 0;
    for (int i = beg; i < end; i++) {
        int c = g_cnt[i];
        g_off[i] = run;
        g_pos[i] = run;
        run += c;
    }
    if (beg < N_NODES && end == N_NODES) g_off[N_NODES] = run;
}

__global__ __launch_bounds__(256) void k_bucket(const int* __restrict__ ei,
                                                const float* __restrict__ ea,
                                                const float* __restrict__ We) {
    int e = blockIdx.x * 256 + threadIdx.x;
    if (e >= N_EDGES) return;
    int src = ei[e];
    int dst = ei[N_EDGES + e];
    float a0 = ea[e * 3 + 0], a1 = ea[e * 3 + 1], a2 = ea[e * 3 + 2];
    float4 b;
    b.x = a0 * We[0] + a1 * We[4] + a2 * We[8];
    b.y = a0 * We[1] + a1 * We[5] + a2 * We[9];
    b.z = a0 * We[2] + a1 * We[6] + a2 * We[10];
    b.w = a0 * We[3] + a1 * We[7] + a2 * We[11];
    int p = atomicAdd(&g_pos[dst], 1);
    g_src[p] = src;
    ((float4*)g_biasS)[p] = b;
}

// ---------------- fused attention + gather: warp/node, 4-edge pipeline -------
__global__ __launch_bounds__(256) void k_gather() {
    int n = blockIdx.x * 8 + (threadIdx.x >> 5);
    if (n >= N_NODES) return;
    int lane = threadIdx.x & 31;
    int h = lane >> 3;
    int beg = g_off[n];
    int end = g_off[n + 1];

    float4 q = ((const float4*)(g_Q + (size_t)n * 128))[lane];
    float4 acc = make_float4(0.f, 0.f, 0.f, 0.f);
    float s = 0.f;

    int i = beg;
    for (; i + 4 <= end; i += 4) {
        int   srcq[4];
        float biasq[4];
        #pragma unroll
        for (int j = 0; j < 4; j++) {
            srcq[j]  = g_src[i + j];
            biasq[j] = g_biasS[(i + j) * 4 + h];
        }
        float4 kq[4], vq[4];
        #pragma unroll
        for (int j = 0; j < 4; j++) {
            kq[j] = ((const float4*)(g_K + (size_t)srcq[j] * 128))[lane];
            vq[j] = ((const float4*)(g_V + (size_t)srcq[j] * 128))[lane];
        }
        float p[4];
        #pragma unroll
        for (int j = 0; j < 4; j++)
            p[j] = q.x * kq[j].x + q.y * kq[j].y + q.z * kq[j].z + q.w * kq[j].w;
        #pragma unroll
        for (int j = 0; j < 4; j++) p[j] += __shfl_xor_sync(0xffffffffu, p[j], 1);
        #pragma unroll
        for (int j = 0; j < 4; j++) p[j] += __shfl_xor_sync(0xffffffffu, p[j], 2);
        #pragma unroll
        for (int j = 0; j < 4; j++) p[j] += __shfl_xor_sync(0xffffffffu, p[j], 4);
        #pragma unroll
        for (int j = 0; j < 4; j++) {
            float a = p[j] * HD_SCALE + biasq[j];
            a = a >= 0.f ? a : 0.2f * a;
            float ex = __expf(a);
            s += ex;
            acc.x = fmaf(vq[j].x, ex, acc.x);
            acc.y = fmaf(vq[j].y, ex, acc.y);
            acc.z = fmaf(vq[j].z, ex, acc.z);
            acc.w = fmaf(vq[j].w, ex, acc.w);
        }
    }
    for (; i < end; i++) {
        int src = g_src[i];
        float bias = g_biasS[i * 4 + h];
        float4 k = ((const float4*)(g_K + (size_t)src * 128))[lane];
        float4 v = ((const float4*)(g_V + (size_t)src * 128))[lane];
        float p = q.x * k.x + q.y * k.y + q.z * k.z + q.w * k.w;
        p += __shfl_xor_sync(0xffffffffu, p, 1);
        p += __shfl_xor_sync(0xffffffffu, p, 2);
        p += __shfl_xor_sync(0xffffffffu, p, 4);
        float a = p * HD_SCALE + bias;
        a = a >= 0.f ? a : 0.2f * a;
        float ex = __expf(a);
        s += ex;
        acc.x = fmaf(v.x, ex, acc.x);
        acc.y = fmaf(v.y, ex, acc.y);
        acc.z = fmaf(v.z, ex, acc.z);
        acc.w = fmaf(v.w, ex, acc.w);
    }

    float inv = 1.f / fmaxf(s, 1e-12f);
    float4* o = (float4*)(g_agg + (size_t)n * 128);
    o[lane] = make_float4(acc.x * inv, acc.y * inv, acc.z * inv, acc.w * inv);
}

// ---------------- launch: 2-way fork (R11 skeleton) ---------------------------
extern "C" void kernel_launch(void* const* d_in, const int* in_sizes, int n_in,
                              void* d_out, int out_size) {
    const float* x  = (const float*)d_in[0];
    const int*   ei = (const int*)d_in[1];
    const float* ea = (const float*)d_in[2];
    const float* Wq = (const float*)d_in[3];
    const float* Wk = (const float*)d_in[4];
    const float* Wv = (const float*)d_in[5];
    const float* We = (const float*)d_in[6];
    const float* Wo = (const float*)d_in[7];
    const float* bo = (const float*)d_in[8];
    const float* Wm = (const float*)d_in[9];
    const float* bm = (const float*)d_in[10];
    float* out = (float*)d_out;

    static cudaStream_t s2 = nullptr;
    static cudaEvent_t evFork = nullptr, evJoin = nullptr;
    static bool init_done = false;
    if (!init_done) {
        cudaFuncSetAttribute(k_qkv_mma, cudaFuncAttributeMaxDynamicSharedMemorySize,
                             SM_MMA_TOT);
        cudaFuncSetAttribute(k_out_mma, cudaFuncAttributeMaxDynamicSharedMemorySize,
                             SM_MMA_TOT);
        cudaStreamCreateWithFlags(&s2, cudaStreamNonBlocking);
        cudaEventCreateWithFlags(&evFork, cudaEventDisableTiming);
        cudaEventCreateWithFlags(&evJoin, cudaEventDisableTiming);
        init_done = true;
    }

    // fork: CSR build chain + fusew on s2, concurrent with QKV GEMM
    cudaEventRecord(evFork, 0);
    cudaStreamWaitEvent(s2, evFork, 0);

    k_init<<<(N_NODES + 255) / 256, 256, 0, s2>>>();
    k_hist<<<(N_EDGES + 255) / 256, 256, 0, s2>>>(ei);
    k_scan<<<1, SCAN_T, 0, s2>>>();
    k_bucket<<<(N_EDGES + 255) / 256, 256, 0, s2>>>(ei, ea, We);
    k_fusew<<<128, 128, 0, s2>>>(Wo, Wm, bo, bm);
    cudaEventRecord(evJoin, s2);

    // main stream: QKV GEMM (64-row blocks, 2 blocks/SM)
    k_qkv_mma<<<(N_NODES + 63) / 64, 256, SM_MMA_TOT>>>(x, Wq, Wk, Wv);

    // join: gather needs Q/K/V + CSR; out needs gather + fusew
    cudaStreamWaitEvent(0, evJoin, 0);
    k_gather<<<(N_NODES + 7) / 8, 256>>>();
    k_out_mma<<<(N_NODES + 63) / 64, 256, SM_MMA_TOT>>>(x, Wm, out);
}

// round 15
// speedup vs baseline: 2.2669x; 2.2669x over previous
#include <cuda_runtime.h>
#include <cuda_bf16.h>
#include <cstdint>

#define N_NODES 50000
#define N_EDGES 800000
#define HD_SCALE 0.17677669529663687f   // 1/sqrt(32)
#define SCAN_T 1024
#define KP 136                           // padded bf16 row stride (272B)

// ---------------- scratch (device globals: no allocation allowed) ----------
__device__ __align__(256) float g_Q[N_NODES * 128];
__device__ __align__(256) float g_K[N_NODES * 128];
__device__ __align__(256) float g_V[N_NODES * 128];
__device__ __align__(256) float g_biasS[N_EDGES * 4];
__device__ __align__(256) float g_agg[N_NODES * 128];
__device__ __align__(256) float g_Wf[128 * 128];
__device__ __align__(256) float g_bf[128];
__device__ __align__(256) int   g_cnt[N_NODES];
__device__ __align__(256) int   g_off[N_NODES + 1];
__device__ __align__(256) int   g_pos[N_NODES];
__device__ __align__(256) int   g_src[N_EDGES];
// pre-split B tiles, n-major KP layout: 0=Wq 1=Wk 2=Wv 3=Wm_top 4=Wf
__device__ __align__(256) __nv_bfloat16 g_BH[5][128 * KP];
__device__ __align__(256) __nv_bfloat16 g_BL[5][128 * KP];

// ---------------- mma.sync helpers (arch-neutral PTX, sm_80+) ---------------
__device__ __forceinline__ uint32_t smem_u32(const void* p) {
    uint32_t a;
    asm("{ .reg .u64 t; cvta.to.shared.u64 t, %1; cvt.u32.u64 %0, t; }"
        : "=r"(a) : "l"(p));
    return a;
}
#define LDM_X4(r, addr)                                                        \
    asm volatile("ldmatrix.sync.aligned.m8n8.x4.shared.b16 {%0,%1,%2,%3}, [%4];" \
                 : "=r"((r)[0]), "=r"((r)[1]), "=r"((r)[2]), "=r"((r)[3])      \
                 : "r"(addr))
#define MMA_B16(c, a, b0, b1)                                                  \
    asm volatile("mma.sync.aligned.m16n8k16.row.col.f32.bf16.bf16.f32 "        \
                 "{%0,%1,%2,%3}, {%4,%5,%6,%7}, {%8,%9}, {%0,%1,%2,%3};"       \
                 : "+f"((c)[0]), "+f"((c)[1]), "+f"((c)[2]), "+f"((c)[3])      \
                 : "r"((a)[0]), "r"((a)[1]), "r"((a)[2]), "r"((a)[3]),         \
                   "r"(b0), "r"(b1))

// smem layout (bytes within dynamic smem); each tile 128 x KP bf16
#define T_BYTES (128 * KP * 2)          // 34816
#define SM_AH 0
#define SM_AL (SM_AH + T_BYTES)
#define SM_BH (SM_AL + T_BYTES)
#define SM_BL (SM_BH + T_BYTES)
#define SM_MMA_TOT (SM_BL + T_BYTES)    // 139264

__device__ __forceinline__ uint32_t pack_bf2(float a, float b) {
    __nv_bfloat162 h = __floats2bfloat162_rn(a, b);
    return *(uint32_t*)&h;
}

__device__ __forceinline__ void load_A(char* sm, const float* __restrict__ src,
                                       int r0, int tid) {
    for (int i = tid; i < 128 * 32; i += 256) {
        int r = i >> 5, c = (i & 31) * 4;
        int gr = r0 + r; if (gr >= N_NODES) gr = N_NODES - 1;
        float4 v = *(const float4*)(src + (size_t)gr * 128 + c);
        float h0 = __bfloat162float(__float2bfloat16(v.x));
        float h1 = __bfloat162float(__float2bfloat16(v.y));
        float h2 = __bfloat162float(__float2bfloat16(v.z));
        float h3 = __bfloat162float(__float2bfloat16(v.w));
        int off = (r * KP + c) * 2;
        *(uint32_t*)(sm + SM_AH + off)     = pack_bf2(v.x, v.y);
        *(uint32_t*)(sm + SM_AH + off + 4) = pack_bf2(v.z, v.w);
        *(uint32_t*)(sm + SM_AL + off)     = pack_bf2(v.x - h0, v.y - h1);
        *(uint32_t*)(sm + SM_AL + off + 4) = pack_bf2(v.z - h2, v.w - h3);
    }
}

// B fill = flat 16B copy of the pre-split tile (layout matches smem exactly)
__device__ __forceinline__ void load_B_pre(char* sm, int t, int tid) {
    const uint4* srcH = (const uint4*)g_BH[t];
    const uint4* srcL = (const uint4*)g_BL[t];
    uint4* dstH = (uint4*)(sm + SM_BH);
    uint4* dstL = (uint4*)(sm + SM_BL);
    for (int i = tid; i < T_BYTES / 16; i += 256) {
        dstH[i] = srcH[i];
        dstL[i] = srcL[i];
    }
}

__device__ __forceinline__ void mma_sweep(uint32_t smb, int lane, int mB, int nB,
                                          float acc[2][8][4]) {
    int aRow = lane & 15;
    int aKH  = (lane >> 4) * 8;
    int bRow = (lane & 7) + ((lane >> 4) << 3);
    int bKH  = ((lane >> 3) & 1) * 8;
    #pragma unroll
    for (int ks = 0; ks < 8; ks++) {
        int k0 = ks * 16;
        uint32_t ah[2][4], al[2][4], bh[4][4], bl[4][4];
        #pragma unroll
        for (int mt = 0; mt < 2; mt++) {
            uint32_t off = (uint32_t)((mB + mt * 16 + aRow) * KP + k0 + aKH) * 2;
            LDM_X4(ah[mt], smb + SM_AH + off);
            LDM_X4(al[mt], smb + SM_AL + off);
        }
        #pragma unroll
        for (int p = 0; p < 4; p++) {
            uint32_t off = (uint32_t)((nB + p * 16 + bRow) * KP + k0 + bKH) * 2;
            LDM_X4(bh[p], smb + SM_BH + off);
            LDM_X4(bl[p], smb + SM_BL + off);
        }
        #pragma unroll
        for (int mt = 0; mt < 2; mt++)
            #pragma unroll
            for (int nt = 0; nt < 8; nt++) {
                int p = nt >> 1, q = (nt & 1) * 2;
                MMA_B16(acc[mt][nt], ah[mt], bh[p][q], bh[p][q + 1]);
                MMA_B16(acc[mt][nt], ah[mt], bl[p][q], bl[p][q + 1]);
                MMA_B16(acc[mt][nt], al[mt], bh[p][q], bh[p][q + 1]);
            }
    }
}

// ---------------- pre-split Wq/Wk/Wv/Wm_top into g_BH/g_BL -------------------
__global__ __launch_bounds__(256) void k_splitW(const float* __restrict__ Wq,
                                                const float* __restrict__ Wk,
                                                const float* __restrict__ Wv,
                                                const float* __restrict__ Wm) {
    int idx = blockIdx.x * 256 + threadIdx.x;   // tile*8192 + n*64 + kpair
    int t = idx >> 13;
    if (t >= 4) return;
    int r = idx & 8191;
    int n = r >> 6;
    int k2 = (r & 63) * 2;
    const float* W = (t == 0) ? Wq : (t == 1) ? Wk : (t == 2) ? Wv : Wm;
    float v0 = W[k2 * 128 + n];
    float v1 = W[(k2 + 1) * 128 + n];
    float h0 = __bfloat162float(__float2bfloat16(v0));
    float h1 = __bfloat162float(__float2bfloat16(v1));
    int off = n * KP + k2;
    *(uint32_t*)&g_BH[t][off] = pack_bf2(v0, v1);
    *(uint32_t*)&g_BL[t][off] = pack_bf2(v0 - h0, v1 - h1);
}

// ---------------- fused QKV GEMM: A tile staged once, loop over 3 W ---------
__global__ __launch_bounds__(256) void k_qkv_mma(const float* __restrict__ x) {
    extern __shared__ char sm[];
    int tid = threadIdx.x, lane = tid & 31, w = tid >> 5;
    int mB = (w >> 1) * 32, nB = (w & 1) * 64;
    int r0 = blockIdx.x * 128;
    uint32_t smb = smem_u32(sm);

    load_A(sm, x, r0, tid);

    int gq = lane >> 2, tq = lane & 3;
    #pragma unroll
    for (int m = 0; m < 3; m++) {
        float* out = (m == 0) ? g_Q : (m == 1) ? g_K : g_V;
        __syncthreads();
        load_B_pre(sm, m, tid);
        __syncthreads();

        float acc[2][8][4];
        #pragma unroll
        for (int mt = 0; mt < 2; mt++)
            #pragma unroll
            for (int nt = 0; nt < 8; nt++)
                #pragma unroll
                for (int i = 0; i < 4; i++) acc[mt][nt][i] = 0.f;

        mma_sweep(smb, lane, mB, nB, acc);

        #pragma unroll
        for (int mt = 0; mt < 2; mt++)
            #pragma unroll
            for (int nt = 0; nt < 8; nt++) {
                int col = nB + nt * 8 + tq * 2;
                int row0 = r0 + mB + mt * 16 + gq;
                if (row0 < N_NODES)
                    *(float2*)(out + (size_t)row0 * 128 + col) =
                        make_float2(acc[mt][nt][0], acc[mt][nt][1]);
                int row1 = row0 + 8;
                if (row1 < N_NODES)
                    *(float2*)(out + (size_t)row1 * 128 + col) =
                        make_float2(acc[mt][nt][2], acc[mt][nt][3]);
            }
    }
}

// ---------------- output GEMM: relu(x@Wm_top + agg@Wf + bf), 2 passes --------
__global__ __launch_bounds__(256) void k_out_mma(const float* __restrict__ x,
                                                 float* __restrict__ out) {
    extern __shared__ char sm[];
    int tid = threadIdx.x, lane = tid & 31, w = tid >> 5;
    int mB = (w >> 1) * 32, nB = (w & 1) * 64;
    int r0 = blockIdx.x * 128;
    uint32_t smb = smem_u32(sm);

    float acc[2][8][4];
    #pragma unroll
    for (int mt = 0; mt < 2; mt++)
        #pragma unroll
        for (int nt = 0; nt < 8; nt++)
            #pragma unroll
            for (int i = 0; i < 4; i++) acc[mt][nt][i] = 0.f;

    #pragma unroll
    for (int pass = 0; pass < 2; pass++) {
        const float* A = pass ? (const float*)g_agg : x;
        __syncthreads();
        load_A(sm, A, r0, tid);
        load_B_pre(sm, pass ? 4 : 3, tid);
        __syncthreads();
        mma_sweep(smb, lane, mB, nB, acc);
    }

    int gq = lane >> 2, tq = lane & 3;
    #pragma unroll
    for (int mt = 0; mt < 2; mt++)
        #pragma unroll
        for (int nt = 0; nt < 8; nt++) {
            int col = nB + nt * 8 + tq * 2;
            float b0 = g_bf[col], b1 = g_bf[col + 1];
            int row0 = r0 + mB + mt * 16 + gq;
            if (row0 < N_NODES)
                *(float2*)(out + (size_t)row0 * 128 + col) =
                    make_float2(fmaxf(acc[mt][nt][0] + b0, 0.f),
                                fmaxf(acc[mt][nt][1] + b1, 0.f));
            int row1 = row0 + 8;
            if (row1 < N_NODES)
                *(float2*)(out + (size_t)row1 * 128 + col) =
                    make_float2(fmaxf(acc[mt][nt][2] + b0, 0.f),
                                fmaxf(acc[mt][nt][3] + b1, 0.f));
        }
}

// ---------------- init / hist / scan / bucket / fusew ------------------------
__global__ void k_init() {
    int i = blockIdx.x * 256 + threadIdx.x;
    if (i < N_NODES) g_cnt[i] = 0;
}

__global__ __launch_bounds__(256) void k_hist(const int* __restrict__ ei) {
    int e = blockIdx.x * 256 + threadIdx.x;
    if (e >= N_EDGES) return;
    atomicAdd(&g_cnt[ei[N_EDGES + e]], 1);
}

// fusew also emits the pre-split Wf tile (index 4)
__global__ void k_fusew(const float* __restrict__ Wo, const float* __restrict__ Wm,
                        const float* __restrict__ bo, const float* __restrict__ bm) {
    int r = blockIdx.x, j = threadIdx.x;
    float acc = 0.f;
    #pragma unroll 8
    for (int k = 0; k < 128; k++)
        acc += Wo[r * 128 + k] * Wm[(128 + k) * 128 + j];
    g_Wf[r * 128 + j] = acc;
    float hf = __bfloat162float(__float2bfloat16(acc));
    g_BH[4][j * KP + r] = __float2bfloat16(acc);
    g_BL[4][j * KP + r] = __float2bfloat16(acc - hf);
    if (r == 0) {
        float b = bm[j];
        #pragma unroll 8
        for (int k = 0; k < 128; k++)
            b += bo[k] * Wm[(128 + k) * 128 + j];
        g_bf[j] = b;
    }
}

__global__ __launch_bounds__(SCAN_T) void k_scan() {
    __shared__ int sh[SCAN_T];
    int t = threadIdx.x;
    const int CHUNK = (N_NODES + SCAN_T - 1) / SCAN_T;
    int beg = t * CHUNK;
    int end = beg + CHUNK < N_NODES ? beg + CHUNK : N_NODES;
    int s = 0;
    for (int i = beg; i < end; i++) s += g_cnt[i];
    sh[t] = s;
    __syncthreads();
    for (int o = 1; o < SCAN_T; o <<= 1) {
        int v = (t >= o) ? sh[t - o] : 0;
        __syncthreads();
        sh[t] += v;
        __syncthreads();
    }
    int run = (t > 0) ? sh[t - 1] : 0;
    for (int i = beg; i < end; i++) {
        int c = g_cnt[i];
        g_off[i] = run;
        g_pos[i] = run;
        run += c;
    }
    if (beg < N_NODES && end == N_NODES) g_off[N_NODES] = run;
}

__global__ __launch_bounds__(256) void k_bucket(const int* __restrict__ ei,
                                                const float* __restrict__ ea,
                                                const float* __restrict__ We) {
    int e = blockIdx.x * 256 + threadIdx.x;
    if (e >= N_EDGES) return;
    int src = ei[e];
    int dst = ei[N_EDGES + e];
    float a0 = ea[e * 3 + 0], a1 = ea[e * 3 + 1], a2 = ea[e * 3 + 2];
    float4 b;
    b.x = a0 * We[0] + a1 * We[4] + a2 * We[8];
    b.y = a0 * We[1] + a1 * We[5] + a2 * We[9];
    b.z = a0 * We[2] + a1 * We[6] + a2 * We[10];
    b.w = a0 * We[3] + a1 * We[7] + a2 * We[11];
    int p = atomicAdd(&g_pos[dst], 1);
    g_src[p] = src;
    ((float4*)g_biasS)[p] = b;
}

// ---------------- fused attention + gather: warp/node, 4-edge pipeline -------
__global__ __launch_bounds__(256) void k_gather() {
    int n = blockIdx.x * 8 + (threadIdx.x >> 5);
    if (n >= N_NODES) return;
    int lane = threadIdx.x & 31;
    int h = lane >> 3;
    int beg = g_off[n];
    int end = g_off[n + 1];

    float4 q = ((const float4*)(g_Q + (size_t)n * 128))[lane];
    float4 acc = make_float4(0.f, 0.f, 0.f, 0.f);
    float s = 0.f;

    int i = beg;
    for (; i + 4 <= end; i += 4) {
        int   srcq[4];
        float biasq[4];
        #pragma unroll
        for (int j = 0; j < 4; j++) {
            srcq[j]  = g_src[i + j];
            biasq[j] = g_biasS[(i + j) * 4 + h];
        }
        float4 kq[4], vq[4];
        #pragma unroll
        for (int j = 0; j < 4; j++) {
            kq[j] = ((const float4*)(g_K + (size_t)srcq[j] * 128))[lane];
            vq[j] = ((const float4*)(g_V + (size_t)srcq[j] * 128))[lane];
        }
        float p[4];
        #pragma unroll
        for (int j = 0; j < 4; j++)
            p[j] = q.x * kq[j].x + q.y * kq[j].y + q.z * kq[j].z + q.w * kq[j].w;
        #pragma unroll
        for (int j = 0; j < 4; j++) p[j] += __shfl_xor_sync(0xffffffffu, p[j], 1);
        #pragma unroll
        for (int j = 0; j < 4; j++) p[j] += __shfl_xor_sync(0xffffffffu, p[j], 2);
        #pragma unroll
        for (int j = 0; j < 4; j++) p[j] += __shfl_xor_sync(0xffffffffu, p[j], 4);
        #pragma unroll
        for (int j = 0; j < 4; j++) {
            float a = p[j] * HD_SCALE + biasq[j];
            a = a >= 0.f ? a : 0.2f * a;
            float ex = __expf(a);
            s += ex;
            acc.x = fmaf(vq[j].x, ex, acc.x);
            acc.y = fmaf(vq[j].y, ex, acc.y);
            acc.z = fmaf(vq[j].z, ex, acc.z);
            acc.w = fmaf(vq[j].w, ex, acc.w);
        }
    }
    for (; i < end; i++) {
        int src = g_src[i];
        float bias = g_biasS[i * 4 + h];
        float4 k = ((const float4*)(g_K + (size_t)src * 128))[lane];
        float4 v = ((const float4*)(g_V + (size_t)src * 128))[lane];
        float p = q.x * k.x + q.y * k.y + q.z * k.z + q.w * k.w;
        p += __shfl_xor_sync(0xffffffffu, p, 1);
        p += __shfl_xor_sync(0xffffffffu, p, 2);
        p += __shfl_xor_sync(0xffffffffu, p, 4);
        float a = p * HD_SCALE + bias;
        a = a >= 0.f ? a : 0.2f * a;
        float ex = __expf(a);
        s += ex;
        acc.x = fmaf(v.x, ex, acc.x);
        acc.y = fmaf(v.y, ex, acc.y);
        acc.z = fmaf(v.z, ex, acc.z);
        acc.w = fmaf(v.w, ex, acc.w);
    }

    float inv = 1.f / fmaxf(s, 1e-12f);
    float4* o = (float4*)(g_agg + (size_t)n * 128);
    o[lane] = make_float4(acc.x * inv, acc.y * inv, acc.z * inv, acc.w * inv);
}

// ---------------- launch: 2-way fork (R11 skeleton) ---------------------------
extern "C" void kernel_launch(void* const* d_in, const int* in_sizes, int n_in,
                              void* d_out, int out_size) {
    const float* x  = (const float*)d_in[0];
    const int*   ei = (const int*)d_in[1];
    const float* ea = (const float*)d_in[2];
    const float* Wq = (const float*)d_in[3];
    const float* Wk = (const float*)d_in[4];
    const float* Wv = (const float*)d_in[5];
    const float* We = (const float*)d_in[6];
    const float* Wo = (const float*)d_in[7];
    const float* bo = (const float*)d_in[8];
    const float* Wm = (const float*)d_in[9];
    const float* bm = (const float*)d_in[10];
    float* out = (float*)d_out;

    static cudaStream_t s2 = nullptr;
    static cudaEvent_t evFork = nullptr, evJoin = nullptr;
    static bool init_done = false;
    if (!init_done) {
        cudaFuncSetAttribute(k_qkv_mma, cudaFuncAttributeMaxDynamicSharedMemorySize,
                             SM_MMA_TOT);
        cudaFuncSetAttribute(k_out_mma, cudaFuncAttributeMaxDynamicSharedMemorySize,
                             SM_MMA_TOT);
        cudaStreamCreateWithFlags(&s2, cudaStreamNonBlocking);
        cudaEventCreateWithFlags(&evFork, cudaEventDisableTiming);
        cudaEventCreateWithFlags(&evJoin, cudaEventDisableTiming);
        init_done = true;
    }

    // fork: CSR build chain + fusew on s2, concurrent with splitW + QKV GEMM
    cudaEventRecord(evFork, 0);
    cudaStreamWaitEvent(s2, evFork, 0);

    k_init<<<(N_NODES + 255) / 256, 256, 0, s2>>>();
    k_hist<<<(N_EDGES + 255) / 256, 256, 0, s2>>>(ei);
    k_scan<<<1, SCAN_T, 0, s2>>>();
    k_bucket<<<(N_EDGES + 255) / 256, 256, 0, s2>>>(ei, ea, We);
    k_fusew<<<128, 128, 0, s2>>>(Wo, Wm, bo, bm);
    cudaEventRecord(evJoin, s2);

    // main stream: pre-split weights, then QKV GEMM
    k_splitW<<<128, 256>>>(Wq, Wk, Wv, Wm);
    k_qkv_mma<<<(N_NODES + 127) / 128, 256, SM_MMA_TOT>>>(x);

    // join: gather needs Q/K/V + CSR; out needs gather + fusew (split Wf)
    cudaStreamWaitEvent(0, evJoin, 0);
    k_gather<<<(N_NODES + 7) / 8, 256>>>();
    k_out_mma<<<(N_NODES + 127) / 128, 256, SM_MMA_TOT>>>(x, out);
}

// round 16
// speedup vs baseline: 2.4188x; 1.0670x over previous
#include <cuda_runtime.h>
#include <cuda_bf16.h>
#include <cuda_fp16.h>
#include <cstdint>

#define N_NODES 50000
#define N_EDGES 800000
#define HD_SCALE 0.17677669529663687f   // 1/sqrt(32)
#define SCAN_T 1024
#define KP 136                           // padded bf16 row stride (272B)

// ---------------- scratch (device globals: no allocation allowed) ----------
__device__ __align__(256) float g_Q[N_NODES * 128];
// interleaved fp16 K/V: per node 32 groups of 16B = {k0..k3, v0..v3} halfs
__device__ __align__(256) uint4 g_KV[N_NODES * 32];
__device__ __align__(256) float g_biasS[N_EDGES * 4];
__device__ __align__(256) float g_agg[N_NODES * 128];
__device__ __align__(256) float g_Wf[128 * 128];
__device__ __align__(256) float g_bf[128];
__device__ __align__(256) int   g_cnt[N_NODES];
__device__ __align__(256) int   g_off[N_NODES + 1];
__device__ __align__(256) int   g_pos[N_NODES];
__device__ __align__(256) int   g_src[N_EDGES];
// pre-split B tiles, n-major KP layout: 0=Wq 1=Wk 2=Wv 3=Wm_top 4=Wf
__device__ __align__(256) __nv_bfloat16 g_BH[5][128 * KP];
__device__ __align__(256) __nv_bfloat16 g_BL[5][128 * KP];

// ---------------- mma.sync helpers (arch-neutral PTX, sm_80+) ---------------
__device__ __forceinline__ uint32_t smem_u32(const void* p) {
    uint32_t a;
    asm("{ .reg .u64 t; cvta.to.shared.u64 t, %1; cvt.u32.u64 %0, t; }"
        : "=r"(a) : "l"(p));
    return a;
}
#define LDM_X4(r, addr)                                                        \
    asm volatile("ldmatrix.sync.aligned.m8n8.x4.shared.b16 {%0,%1,%2,%3}, [%4];" \
                 : "=r"((r)[0]), "=r"((r)[1]), "=r"((r)[2]), "=r"((r)[3])      \
                 : "r"(addr))
#define MMA_B16(c, a, b0, b1)                                                  \
    asm volatile("mma.sync.aligned.m16n8k16.row.col.f32.bf16.bf16.f32 "        \
                 "{%0,%1,%2,%3}, {%4,%5,%6,%7}, {%8,%9}, {%0,%1,%2,%3};"       \
                 : "+f"((c)[0]), "+f"((c)[1]), "+f"((c)[2]), "+f"((c)[3])      \
                 : "r"((a)[0]), "r"((a)[1]), "r"((a)[2]), "r"((a)[3]),         \
                   "r"(b0), "r"(b1))

// smem layout (bytes within dynamic smem); each tile 128 x KP bf16
#define T_BYTES (128 * KP * 2)          // 34816
#define SM_AH 0
#define SM_AL (SM_AH + T_BYTES)
#define SM_BH (SM_AL + T_BYTES)
#define SM_BL (SM_BH + T_BYTES)
#define SM_MMA_TOT (SM_BL + T_BYTES)    // 139264

__device__ __forceinline__ uint32_t pack_bf2(float a, float b) {
    __nv_bfloat162 h = __floats2bfloat162_rn(a, b);
    return *(uint32_t*)&h;
}

__device__ __forceinline__ void load_A(char* sm, const float* __restrict__ src,
                                       int r0, int tid) {
    for (int i = tid; i < 128 * 32; i += 256) {
        int r = i >> 5, c = (i & 31) * 4;
        int gr = r0 + r; if (gr >= N_NODES) gr = N_NODES - 1;
        float4 v = *(const float4*)(src + (size_t)gr * 128 + c);
        float h0 = __bfloat162float(__float2bfloat16(v.x));
        float h1 = __bfloat162float(__float2bfloat16(v.y));
        float h2 = __bfloat162float(__float2bfloat16(v.z));
        float h3 = __bfloat162float(__float2bfloat16(v.w));
        int off = (r * KP + c) * 2;
        *(uint32_t*)(sm + SM_AH + off)     = pack_bf2(v.x, v.y);
        *(uint32_t*)(sm + SM_AH + off + 4) = pack_bf2(v.z, v.w);
        *(uint32_t*)(sm + SM_AL + off)     = pack_bf2(v.x - h0, v.y - h1);
        *(uint32_t*)(sm + SM_AL + off + 4) = pack_bf2(v.z - h2, v.w - h3);
    }
}

// B fill = flat 16B copy of the pre-split tile (layout matches smem exactly)
__device__ __forceinline__ void load_B_pre(char* sm, int t, int tid) {
    const uint4* srcH = (const uint4*)g_BH[t];
    const uint4* srcL = (const uint4*)g_BL[t];
    uint4* dstH = (uint4*)(sm + SM_BH);
    uint4* dstL = (uint4*)(sm + SM_BL);
    for (int i = tid; i < T_BYTES / 16; i += 256) {
        dstH[i] = srcH[i];
        dstL[i] = srcL[i];
    }
}

__device__ __forceinline__ void mma_sweep(uint32_t smb, int lane, int mB, int nB,
                                          float acc[2][8][4]) {
    int aRow = lane & 15;
    int aKH  = (lane >> 4) * 8;
    int bRow = (lane & 7) + ((lane >> 4) << 3);
    int bKH  = ((lane >> 3) & 1) * 8;
    #pragma unroll
    for (int ks = 0; ks < 8; ks++) {
        int k0 = ks * 16;
        uint32_t ah[2][4], al[2][4], bh[4][4], bl[4][4];
        #pragma unroll
        for (int mt = 0; mt < 2; mt++) {
            uint32_t off = (uint32_t)((mB + mt * 16 + aRow) * KP + k0 + aKH) * 2;
            LDM_X4(ah[mt], smb + SM_AH + off);
            LDM_X4(al[mt], smb + SM_AL + off);
        }
        #pragma unroll
        for (int p = 0; p < 4; p++) {
            uint32_t off = (uint32_t)((nB + p * 16 + bRow) * KP + k0 + bKH) * 2;
            LDM_X4(bh[p], smb + SM_BH + off);
            LDM_X4(bl[p], smb + SM_BL + off);
        }
        #pragma unroll
        for (int mt = 0; mt < 2; mt++)
            #pragma unroll
            for (int nt = 0; nt < 8; nt++) {
                int p = nt >> 1, q = (nt & 1) * 2;
                MMA_B16(acc[mt][nt], ah[mt], bh[p][q], bh[p][q + 1]);
                MMA_B16(acc[mt][nt], ah[mt], bl[p][q], bl[p][q + 1]);
                MMA_B16(acc[mt][nt], al[mt], bh[p][q], bh[p][q + 1]);
            }
    }
}

// ---------------- pre-split Wq/Wk/Wv/Wm_top into g_BH/g_BL -------------------
__global__ __launch_bounds__(256) void k_splitW(const float* __restrict__ Wq,
                                                const float* __restrict__ Wk,
                                                const float* __restrict__ Wv,
                                                const float* __restrict__ Wm) {
    int idx = blockIdx.x * 256 + threadIdx.x;   // tile*8192 + n*64 + kpair
    int t = idx >> 13;
    if (t >= 4) return;
    int r = idx & 8191;
    int n = r >> 6;
    int k2 = (r & 63) * 2;
    const float* W = (t == 0) ? Wq : (t == 1) ? Wk : (t == 2) ? Wv : Wm;
    float v0 = W[k2 * 128 + n];
    float v1 = W[(k2 + 1) * 128 + n];
    float h0 = __bfloat162float(__float2bfloat16(v0));
    float h1 = __bfloat162float(__float2bfloat16(v1));
    int off = n * KP + k2;
    *(uint32_t*)&g_BH[t][off] = pack_bf2(v0, v1);
    *(uint32_t*)&g_BL[t][off] = pack_bf2(v0 - h0, v1 - h1);
}

// ---------------- fused QKV GEMM: A tile staged once, loop over 3 W ---------
// m=0 -> Q (fp32); m=1 -> K, m=2 -> V (fp16, interleaved into g_KV)
__global__ __launch_bounds__(256) void k_qkv_mma(const float* __restrict__ x) {
    extern __shared__ char sm[];
    int tid = threadIdx.x, lane = tid & 31, w = tid >> 5;
    int mB = (w >> 1) * 32, nB = (w & 1) * 64;
    int r0 = blockIdx.x * 128;
    uint32_t smb = smem_u32(sm);

    load_A(sm, x, r0, tid);

    int gq = lane >> 2, tq = lane & 3;
    #pragma unroll
    for (int m = 0; m < 3; m++) {
        __syncthreads();
        load_B_pre(sm, m, tid);
        __syncthreads();

        float acc[2][8][4];
        #pragma unroll
        for (int mt = 0; mt < 2; mt++)
            #pragma unroll
            for (int nt = 0; nt < 8; nt++)
                #pragma unroll
                for (int i = 0; i < 4; i++) acc[mt][nt][i] = 0.f;

        mma_sweep(smb, lane, mB, nB, acc);

        #pragma unroll
        for (int mt = 0; mt < 2; mt++)
            #pragma unroll
            for (int nt = 0; nt < 8; nt++) {
                int col = nB + nt * 8 + tq * 2;
                int row0 = r0 + mB + mt * 16 + gq;
                int row1 = row0 + 8;
                if (m == 0) {
                    if (row0 < N_NODES)
                        *(float2*)(g_Q + (size_t)row0 * 128 + col) =
                            make_float2(acc[mt][nt][0], acc[mt][nt][1]);
                    if (row1 < N_NODES)
                        *(float2*)(g_Q + (size_t)row1 * 128 + col) =
                            make_float2(acc[mt][nt][2], acc[mt][nt][3]);
                } else {
                    // byte offset within node row: 16*(col/4) + 2*(col%4), V at +8
                    int boff = 16 * (col >> 2) + ((col & 3) * 2) + (m == 2 ? 8 : 0);
                    if (row0 < N_NODES) {
                        __half2 h = __floats2half2_rn(acc[mt][nt][0], acc[mt][nt][1]);
                        *(uint32_t*)((char*)g_KV + (size_t)row0 * 512 + boff) =
                            *(uint32_t*)&h;
                    }
                    if (row1 < N_NODES) {
                        __half2 h = __floats2half2_rn(acc[mt][nt][2], acc[mt][nt][3]);
                        *(uint32_t*)((char*)g_KV + (size_t)row1 * 512 + boff) =
                            *(uint32_t*)&h;
                    }
                }
            }
    }
}

// ---------------- output GEMM: relu(x@Wm_top + agg@Wf + bf), 2 passes --------
__global__ __launch_bounds__(256) void k_out_mma(const float* __restrict__ x,
                                                 float* __restrict__ out) {
    extern __shared__ char sm[];
    int tid = threadIdx.x, lane = tid & 31, w = tid >> 5;
    int mB = (w >> 1) * 32, nB = (w & 1) * 64;
    int r0 = blockIdx.x * 128;
    uint32_t smb = smem_u32(sm);

    float acc[2][8][4];
    #pragma unroll
    for (int mt = 0; mt < 2; mt++)
        #pragma unroll
        for (int nt = 0; nt < 8; nt++)
            #pragma unroll
            for (int i = 0; i < 4; i++) acc[mt][nt][i] = 0.f;

    #pragma unroll
    for (int pass = 0; pass < 2; pass++) {
        const float* A = pass ? (const float*)g_agg : x;
        __syncthreads();
        load_A(sm, A, r0, tid);
        load_B_pre(sm, pass ? 4 : 3, tid);
        __syncthreads();
        mma_sweep(smb, lane, mB, nB, acc);
    }

    int gq = lane >> 2, tq = lane & 3;
    #pragma unroll
    for (int mt = 0; mt < 2; mt++)
        #pragma unroll
        for (int nt = 0; nt < 8; nt++) {
            int col = nB + nt * 8 + tq * 2;
            float b0 = g_bf[col], b1 = g_bf[col + 1];
            int row0 = r0 + mB + mt * 16 + gq;
            if (row0 < N_NODES)
                *(float2*)(out + (size_t)row0 * 128 + col) =
                    make_float2(fmaxf(acc[mt][nt][0] + b0, 0.f),
                                fmaxf(acc[mt][nt][1] + b1, 0.f));
            int row1 = row0 + 8;
            if (row1 < N_NODES)
                *(float2*)(out + (size_t)row1 * 128 + col) =
                    make_float2(fmaxf(acc[mt][nt][2] + b0, 0.f),
                                fmaxf(acc[mt][nt][3] + b1, 0.f));
        }
}

// ---------------- init / hist / scan / bucket / fusew ------------------------
__global__ void k_init() {
    int i = blockIdx.x * 256 + threadIdx.x;
    if (i < N_NODES) g_cnt[i] = 0;
}

__global__ __launch_bounds__(256) void k_hist(const int* __restrict__ ei) {
    int e = blockIdx.x * 256 + threadIdx.x;
    if (e >= N_EDGES) return;
    atomicAdd(&g_cnt[ei[N_EDGES + e]], 1);
}

// fusew also emits the pre-split Wf tile (index 4)
__global__ void k_fusew(const float* __restrict__ Wo, const float* __restrict__ Wm,
                        const float* __restrict__ bo, const float* __restrict__ bm) {
    int r = blockIdx.x, j = threadIdx.x;
    float acc = 0.f;
    #pragma unroll 8
    for (int k = 0; k < 128; k++)
        acc += Wo[r * 128 + k] * Wm[(128 + k) * 128 + j];
    g_Wf[r * 128 + j] = acc;
    float hf = __bfloat162float(__float2bfloat16(acc));
    g_BH[4][j * KP + r] = __float2bfloat16(acc);
    g_BL[4][j * KP + r] = __float2bfloat16(acc - hf);
    if (r == 0) {
        float b = bm[j];
        #pragma unroll 8
        for (int k = 0; k < 128; k++)
            b += bo[k] * Wm[(128 + k) * 128 + j];
        g_bf[j] = b;
    }
}

__global__ __launch_bounds__(SCAN_T) void k_scan() {
    __shared__ int sh[SCAN_T];
    int t = threadIdx.x;
    const int CHUNK = (N_NODES + SCAN_T - 1) / SCAN_T;
    int beg = t * CHUNK;
    int end = beg + CHUNK < N_NODES ? beg + CHUNK : N_NODES;
    int s = 0;
    for (int i = beg; i < end; i++) s += g_cnt[i];
    sh[t] = s;
    __syncthreads();
    for (int o = 1; o < SCAN_T; o <<= 1) {
        int v = (t >= o) ? sh[t - o] : 0;
        __syncthreads();
        sh[t] += v;
        __syncthreads();
    }
    int run = (t > 0) ? sh[t - 1] : 0;
    for (int i = beg; i < end; i++) {
        int c = g_cnt[i];
        g_off[i] = run;
        g_pos[i] = run;
        run += c;
    }
    if (beg < N_NODES && end == N_NODES) g_off[N_NODES] = run;
}

__global__ __launch_bounds__(256) void k_bucket(const int* __restrict__ ei,
                                                const float* __restrict__ ea,
                                                const float* __restrict__ We) {
    int e = blockIdx.x * 256 + threadIdx.x;
    if (e >= N_EDGES) return;
    int src = ei[e];
    int dst = ei[N_EDGES + e];
    float a0 = ea[e * 3 + 0], a1 = ea[e * 3 + 1], a2 = ea[e * 3 + 2];
    float4 b;
    b.x = a0 * We[0] + a1 * We[4] + a2 * We[8];
    b.y = a0 * We[1] + a1 * We[5] + a2 * We[9];
    b.z = a0 * We[2] + a1 * We[6] + a2 * We[10];
    b.w = a0 * We[3] + a1 * We[7] + a2 * We[11];
    int p = atomicAdd(&g_pos[dst], 1);
    g_src[p] = src;
    ((float4*)g_biasS)[p] = b;
}

// ---------------- fused attention + gather: warp/node, fp16 K/V --------------
__global__ __launch_bounds__(256) void k_gather() {
    int n = blockIdx.x * 8 + (threadIdx.x >> 5);
    if (n >= N_NODES) return;
    int lane = threadIdx.x & 31;
    int h = lane >> 3;
    int beg = g_off[n];
    int end = g_off[n + 1];

    float4 q = ((const float4*)(g_Q + (size_t)n * 128))[lane];
    float4 acc = make_float4(0.f, 0.f, 0.f, 0.f);
    float s = 0.f;

    int i = beg;
    for (; i + 4 <= end; i += 4) {
        int   srcq[4];
        float biasq[4];
        #pragma unroll
        for (int j = 0; j < 4; j++) {
            srcq[j]  = g_src[i + j];
            biasq[j] = g_biasS[(i + j) * 4 + h];
        }
        uint4 kvq[4];
        #pragma unroll
        for (int j = 0; j < 4; j++)
            kvq[j] = g_KV[(size_t)srcq[j] * 32 + lane];   // one 16B load: k4+v4

        float p[4];
        float2 v01[4], v23[4];
        #pragma unroll
        for (int j = 0; j < 4; j++) {
            float2 k01 = __half22float2(*(__half2*)&kvq[j].x);
            float2 k23 = __half22float2(*(__half2*)&kvq[j].y);
            v01[j] = __half22float2(*(__half2*)&kvq[j].z);
            v23[j] = __half22float2(*(__half2*)&kvq[j].w);
            p[j] = q.x * k01.x + q.y * k01.y + q.z * k23.x + q.w * k23.y;
        }
        #pragma unroll
        for (int j = 0; j < 4; j++) p[j] += __shfl_xor_sync(0xffffffffu, p[j], 1);
        #pragma unroll
        for (int j = 0; j < 4; j++) p[j] += __shfl_xor_sync(0xffffffffu, p[j], 2);
        #pragma unroll
        for (int j = 0; j < 4; j++) p[j] += __shfl_xor_sync(0xffffffffu, p[j], 4);
        #pragma unroll
        for (int j = 0; j < 4; j++) {
            float a = p[j] * HD_SCALE + biasq[j];
            a = a >= 0.f ? a : 0.2f * a;
            float ex = __expf(a);
            s += ex;
            acc.x = fmaf(v01[j].x, ex, acc.x);
            acc.y = fmaf(v01[j].y, ex, acc.y);
            acc.z = fmaf(v23[j].x, ex, acc.z);
            acc.w = fmaf(v23[j].y, ex, acc.w);
        }
    }
    for (; i < end; i++) {
        int src = g_src[i];
        float bias = g_biasS[i * 4 + h];
        uint4 kv = g_KV[(size_t)src * 32 + lane];
        float2 k01 = __half22float2(*(__half2*)&kv.x);
        float2 k23 = __half22float2(*(__half2*)&kv.y);
        float2 v01 = __half22float2(*(__half2*)&kv.z);
        float2 v23 = __half22float2(*(__half2*)&kv.w);
        float p = q.x * k01.x + q.y * k01.y + q.z * k23.x + q.w * k23.y;
        p += __shfl_xor_sync(0xffffffffu, p, 1);
        p += __shfl_xor_sync(0xffffffffu, p, 2);
        p += __shfl_xor_sync(0xffffffffu, p, 4);
        float a = p * HD_SCALE + bias;
        a = a >= 0.f ? a : 0.2f * a;
        float ex = __expf(a);
        s += ex;
        acc.x = fmaf(v01.x, ex, acc.x);
        acc.y = fmaf(v01.y, ex, acc.y);
        acc.z = fmaf(v23.x, ex, acc.z);
        acc.w = fmaf(v23.y, ex, acc.w);
    }

    float inv = 1.f / fmaxf(s, 1e-12f);
    float4* o = (float4*)(g_agg + (size_t)n * 128);
    o[lane] = make_float4(acc.x * inv, acc.y * inv, acc.z * inv, acc.w * inv);
}

// ---------------- launch: 2-way fork (R11/R15 skeleton) ----------------------
extern "C" void kernel_launch(void* const* d_in, const int* in_sizes, int n_in,
                              void* d_out, int out_size) {
    const float* x  = (const float*)d_in[0];
    const int*   ei = (const int*)d_in[1];
    const float* ea = (const float*)d_in[2];
    const float* Wq = (const float*)d_in[3];
    const float* Wk = (const float*)d_in[4];
    const float* Wv = (const float*)d_in[5];
    const float* We = (const float*)d_in[6];
    const float* Wo = (const float*)d_in[7];
    const float* bo = (const float*)d_in[8];
    const float* Wm = (const float*)d_in[9];
    const float* bm = (const float*)d_in[10];
    float* out = (float*)d_out;

    static cudaStream_t s2 = nullptr;
    static cudaEvent_t evFork = nullptr, evJoin = nullptr;
    static bool init_done = false;
    if (!init_done) {
        cudaFuncSetAttribute(k_qkv_mma, cudaFuncAttributeMaxDynamicSharedMemorySize,
                             SM_MMA_TOT);
        cudaFuncSetAttribute(k_out_mma, cudaFuncAttributeMaxDynamicSharedMemorySize,
                             SM_MMA_TOT);
        cudaStreamCreateWithFlags(&s2, cudaStreamNonBlocking);
        cudaEventCreateWithFlags(&evFork, cudaEventDisableTiming);
        cudaEventCreateWithFlags(&evJoin, cudaEventDisableTiming);
        init_done = true;
    }

    // fork: CSR build chain + fusew on s2, concurrent with splitW + QKV GEMM
    cudaEventRecord(evFork, 0);
    cudaStreamWaitEvent(s2, evFork, 0);

    k_init<<<(N_NODES + 255) / 256, 256, 0, s2>>>();
    k_hist<<<(N_EDGES + 255) / 256, 256, 0, s2>>>(ei);
    k_scan<<<1, SCAN_T, 0, s2>>>();
    k_bucket<<<(N_EDGES + 255) / 256, 256, 0, s2>>>(ei, ea, We);
    k_fusew<<<128, 128, 0, s2>>>(Wo, Wm, bo, bm);
    cudaEventRecord(evJoin, s2);

    // main stream: pre-split weights, then QKV GEMM
    k_splitW<<<128, 256>>>(Wq, Wk, Wv, Wm);
    k_qkv_mma<<<(N_NODES + 127) / 128, 256, SM_MMA_TOT>>>(x);

    // join: gather needs Q/KV + CSR; out needs gather + fusew (split Wf)
    cudaStreamWaitEvent(0, evJoin, 0);
    k_gather<<<(N_NODES + 7) / 8, 256>>>();
    k_out_mma<<<(N_NODES + 127) / 128, 256, SM_MMA_TOT>>>(x, out);
}